// round 6
// baseline (speedup 1.0000x reference)
#include <cuda_runtime.h>
#include <cuda_fp16.h>
#include <cstdint>

// Problem constants
#define B_      4
#define N_      4096
#define K_      32
#define H_      128
#define NODES   (B_ * N_)        // 16384
#define EDGES   (NODES * K_)     // 524288
#define NTILES  (NODES / 4)      // 4096 tiles of 128 edges (4 nodes)
#define NCH     256              // chunks per batch for norm (16 nodes each)
#define LDS2    144              // proj kernel smem row stride (floats)

// edge kernel: 3 half-precision regions [128 rows x 256B], XOR-swizzled
#define HROW    256              // bytes per row (128 halfs)
#define HREG    (128 * HROW)     // 32768 B
static const int EDGE_SMEM = 3 * HREG + 1024;
static const int PROJ_SMEM = 3 * 128 * LDS2 * 4;

// Scratch (no cudaMalloc allowed)
__device__ float g_P[NODES * H_];     // enc @ W0[:H]; reused as g_upd after edge kernel
__device__ float g_S[NODES * H_];     // enc @ W0[H:2H] + b0
__device__ float g_msum[NODES * H_];
__device__ float g_vcnt[NODES];
__device__ float g_ps [B_ * NCH * H_];
__device__ float g_ps2[B_ * NCH * H_];
__device__ float g_pc [B_ * NCH];
__device__ float g_mean[B_ * H_];
__device__ float g_rstd[B_ * H_];
#define g_upd g_P

// ---------------------------------------------------------------- helpers
__device__ __forceinline__ float to_tf32(float x) {
    uint32_t u;
    asm("cvt.rna.tf32.f32 %0, %1;" : "=r"(u) : "f"(x));
    return __uint_as_float(u);
}
__device__ __forceinline__ float gelu_erf(float x) {
    return 0.5f * x * (1.0f + erff(x * 0.70710678118654752f));
}
__device__ __forceinline__ int pidx(int k) {   // proj kernel permuted-k layout
    return ((k >> 4) << 4) + ((k & 3) << 2) + ((k >> 2) & 3);
}
__device__ __forceinline__ uint32_t smem_u32(const void* p) {
    uint32_t r;
    asm("{ .reg .u64 t; cvta.to.shared.u64 t, %1; cvt.u32.u64 %0, t; }" : "=r"(r) : "l"(p));
    return r;
}
__device__ __forceinline__ uint32_t h2u(__half2 h) { return *(uint32_t*)&h; }

#define LDSM_X4(r0, r1, r2, r3, addr) \
    asm volatile("ldmatrix.sync.aligned.m8n8.x4.shared.b16 {%0,%1,%2,%3}, [%4];" \
                 : "=r"(r0), "=r"(r1), "=r"(r2), "=r"(r3) : "r"(addr))

__device__ __forceinline__ void mma16(float* c, const uint32_t* a, const uint32_t* b) {
    asm volatile(
        "mma.sync.aligned.m16n8k16.row.col.f32.f16.f16.f32 "
        "{%0,%1,%2,%3},{%4,%5,%6,%7},{%8,%9},{%0,%1,%2,%3};\n"
        : "+f"(c[0]), "+f"(c[1]), "+f"(c[2]), "+f"(c[3])
        : "r"(a[0]), "r"(a[1]), "r"(a[2]), "r"(a[3]), "r"(b[0]), "r"(b[1]));
}

// fp16 warp GEMM: warp tile 32 rows x 32 cols, K=128, via ldmatrix.x4.
// A region rows = edges, W region rows = output cols; both [row][k] halfs,
// 16B chunk swizzle: chunk' = chunk ^ (row & 7).
__device__ __forceinline__ void warp_gemm_h32(uint32_t sA, uint32_t sW,
                                              float (&acc)[2][4][4],
                                              int rowA0, int colB0, int lane) {
    int q = lane & 7, mat = lane >> 3;
    int kaddA = mat >> 1;          // A: mats 0,1 -> kchunk+0 ; 2,3 -> +1
    int kaddB = mat & 1;           // B: mats 0,2 -> kchunk+0 ; 1,3 -> +1
    uint32_t aBase[2]; int aR7[2];
#pragma unroll
    for (int i = 0; i < 2; i++) {
        int row = rowA0 + i * 16 + q + (mat & 1) * 8;
        aBase[i] = sA + row * HROW;
        aR7[i] = (row & 7) << 4;
    }
    uint32_t bBase[2]; int bR7[2];
#pragma unroll
    for (int p = 0; p < 2; p++) {
        int n = colB0 + p * 16 + q + (mat >> 1) * 8;
        bBase[p] = sW + n * HROW;
        bR7[p] = (n & 7) << 4;
    }
#pragma unroll
    for (int s = 0; s < 8; s++) {
        uint32_t a[2][4];
#pragma unroll
        for (int i = 0; i < 2; i++)
            LDSM_X4(a[i][0], a[i][1], a[i][2], a[i][3],
                    aBase[i] + ((((2 * s + kaddA) << 4)) ^ aR7[i]));
#pragma unroll
        for (int p = 0; p < 2; p++) {
            uint32_t b[4];
            LDSM_X4(b[0], b[1], b[2], b[3],
                    bBase[p] + ((((2 * s + kaddB) << 4)) ^ bR7[p]));
#pragma unroll
            for (int i = 0; i < 2; i++) {
                mma16(acc[i][2 * p],     a[i], &b[0]);
                mma16(acc[i][2 * p + 1], a[i], &b[2]);
            }
        }
    }
}

// ---------------------------------------------------------------- proj (tf32 mma.sync)
__device__ __forceinline__ void mma8(float* c, const uint32_t* a, const uint32_t* b) {
    asm volatile(
        "mma.sync.aligned.m16n8k8.row.col.f32.tf32.tf32.f32 "
        "{%0,%1,%2,%3},{%4,%5,%6,%7},{%8,%9},{%0,%1,%2,%3};\n"
        : "+f"(c[0]), "+f"(c[1]), "+f"(c[2]), "+f"(c[3])
        : "r"(a[0]), "r"(a[1]), "r"(a[2]), "r"(a[3]), "r"(b[0]), "r"(b[1]));
}
template <int NJ>
__device__ __forceinline__ void warp_gemm_p(const float* __restrict__ sAv,
                                            const float* __restrict__ sWv,
                                            float (&acc)[2][NJ][4],
                                            int rowA0, int colB0, int gid, int tig) {
#pragma unroll
    for (int j = 0; j < 8; j++) {
        int fo = (j * 4 + tig) * 4;
        float4 a4[2][2];
#pragma unroll
        for (int i = 0; i < 2; i++) {
            const float* ap = sAv + (rowA0 + i * 16 + gid) * LDS2 + fo;
            a4[i][0] = *(const float4*)ap;
            a4[i][1] = *(const float4*)(ap + 8 * LDS2);
        }
#pragma unroll
        for (int jj = 0; jj < NJ; jj++) {
            float4 b4 = *(const float4*)(sWv + (colB0 + jj * 8 + gid) * LDS2 + fo);
            uint32_t b0[2] = {__float_as_uint(b4.x), __float_as_uint(b4.y)};
            uint32_t b1[2] = {__float_as_uint(b4.z), __float_as_uint(b4.w)};
#pragma unroll
            for (int i = 0; i < 2; i++) {
                uint32_t a0[4] = {__float_as_uint(a4[i][0].x), __float_as_uint(a4[i][1].x),
                                  __float_as_uint(a4[i][0].y), __float_as_uint(a4[i][1].y)};
                uint32_t a1[4] = {__float_as_uint(a4[i][0].z), __float_as_uint(a4[i][1].z),
                                  __float_as_uint(a4[i][0].w), __float_as_uint(a4[i][1].w)};
                mma8(acc[i][jj], a0, b0);
                mma8(acc[i][jj], a1, b1);
            }
        }
    }
}

__global__ void __launch_bounds__(256, 1)
proj_kernel(const float* __restrict__ atom, const float* __restrict__ mask,
            const float* __restrict__ W0, const float* __restrict__ b0) {
    extern __shared__ float smem[];
    float* sA  = smem;
    float* sWa = smem + 128 * LDS2;
    float* sWb = smem + 2 * 128 * LDS2;
    __shared__ float sB0[128];

    int t = threadIdx.x, lane = t & 31, w = t >> 5;
    int wm = w >> 1, wn = w & 1, gid = lane >> 2, tig = lane & 3;

    if (t < 128) sB0[t] = b0[t];
    for (int i = t; i < 128 * 128; i += 256) {
        int k = i >> 7, n = i & 127;
        int p = n * LDS2 + pidx(k);
        sWa[p] = to_tf32(W0[i]);
        sWb[p] = to_tf32(W0[128 * 128 + i]);
    }
    {
        int r = t >> 1;
        int grow = blockIdx.x * 128 + r;
        float m = mask[grow];
        int c0 = (t & 1) * 64;
        const float4* src = (const float4*)(atom + (size_t)grow * H_);
#pragma unroll 4
        for (int c = c0; c < c0 + 64; c += 4) {
            float4 a = src[c >> 2];
            int base = r * LDS2 + ((c >> 4) << 4) + ((c >> 2) & 3);
            sA[base + 0]  = to_tf32(a.x * m);
            sA[base + 4]  = to_tf32(a.y * m);
            sA[base + 8]  = to_tf32(a.z * m);
            sA[base + 12] = to_tf32(a.w * m);
        }
    }
    __syncthreads();

    float acc[2][8][4];
#pragma unroll
    for (int i = 0; i < 2; i++)
#pragma unroll
        for (int j = 0; j < 8; j++)
#pragma unroll
            for (int q = 0; q < 4; q++) acc[i][j][q] = 0.f;
    warp_gemm_p<8>(sA, sWa, acc, wm * 32, wn * 64, gid, tig);
#pragma unroll
    for (int i = 0; i < 2; i++)
#pragma unroll
        for (int j = 0; j < 8; j++) {
            int col = wn * 64 + j * 8 + 2 * tig;
            int r = blockIdx.x * 128 + wm * 32 + i * 16 + gid;
            *(float2*)(g_P + (size_t)r * H_ + col)       = make_float2(acc[i][j][0], acc[i][j][1]);
            *(float2*)(g_P + (size_t)(r + 8) * H_ + col) = make_float2(acc[i][j][2], acc[i][j][3]);
        }
#pragma unroll
    for (int i = 0; i < 2; i++)
#pragma unroll
        for (int j = 0; j < 8; j++)
#pragma unroll
            for (int q = 0; q < 4; q++) acc[i][j][q] = 0.f;
    warp_gemm_p<8>(sA, sWb, acc, wm * 32, wn * 64, gid, tig);
#pragma unroll
    for (int i = 0; i < 2; i++)
#pragma unroll
        for (int j = 0; j < 8; j++) {
            int col = wn * 64 + j * 8 + 2 * tig;
            int r = blockIdx.x * 128 + wm * 32 + i * 16 + gid;
            float be = sB0[col], bo = sB0[col + 1];
            *(float2*)(g_S + (size_t)r * H_ + col)       = make_float2(acc[i][j][0] + be, acc[i][j][1] + bo);
            *(float2*)(g_S + (size_t)(r + 8) * H_ + col) = make_float2(acc[i][j][2] + be, acc[i][j][3] + bo);
        }
}

// ------------------------------------------------- persistent fused edge MLP (fp16 + ldmatrix)
// 512 threads = 16 warps (4 row-bands x 4 col-quarters, 32x32 warp tiles), 2 CTAs/SM.
__global__ void __launch_bounds__(512, 2)
edge_kernel(const float* __restrict__ dist, const int* __restrict__ eidx,
            const float* __restrict__ W0, const float* __restrict__ W1,
            const float* __restrict__ b1, const float* __restrict__ W2,
            const float* __restrict__ b2) {
    extern __shared__ char dsm[];
    __shared__ float sValid[128], sW0c[128], sB1[128], sB2[128];

    uint32_t dynBase = smem_u32(dsm);
    uint32_t pad = (1024u - (dynBase & 1023u)) & 1023u;
    uint32_t sAaddr  = dynBase + pad;
    uint32_t sW1addr = sAaddr + HREG;
    uint32_t sW2addr = sAaddr + 2 * HREG;
    char* aBase  = dsm + pad;
    char* w1Base = aBase + HREG;
    char* w2Base = aBase + 2 * HREG;

    int t = threadIdx.x, lane = t & 31, w = t >> 5;
    int wm = w >> 2, wn = w & 3, gid = lane >> 2, tig = lane & 3;

    if (t < 128) {
        sW0c[t] = W0[256 * 128 + t];
        sB1[t]  = b1[t];
        sB2[t]  = b2[t];
    }
    // one-time weight staging: region row n holds W[.][n] over k, swizzled halfs
    for (int i = t; i < 128 * 128; i += 512) {
        int k = i >> 7, n = i & 127;
        uint32_t off = (uint32_t)(n * HROW + ((((k >> 3) ^ (n & 7)) << 4)) + (k & 7) * 2);
        *(__half*)(w1Base + off) = __float2half_rn(W1[i]);
        *(__half*)(w2Base + off) = __float2half_rn(W2[i]);
    }
    __syncthreads();

    for (int tile = blockIdx.x; tile < NTILES; tile += gridDim.x) {
        // ---- phase A: gather + layer-1 epilogue -> h0 halfs into A region
        {
            int e = t >> 2;                      // edge row (4 threads per row)
            int sub = t & 3;                     // quarter-row (32 cols)
            int gnode = tile * 4 + (e >> 5);
            int eid = gnode * K_ + (e & 31);
            int idx = __ldg(eidx + eid);
            float valid = (idx >= 0) ? 1.0f : 0.0f;
            int src = (gnode & ~(N_ - 1)) + (idx >= 0 ? idx : 0);
            float d = __ldg(dist + eid);
            if (sub == 0) sValid[e] = valid;
            const float4* pp = (const float4*)(g_P + (size_t)src * H_);
            const float4* sp = (const float4*)(g_S + (size_t)gnode * H_);
#pragma unroll
            for (int it = 0; it < 4; it++) {
                int c = sub * 4 + it;            // 16B chunk 0..15
                int k0 = c * 8;
                float4 p0 = pp[c * 2],     s0 = sp[c * 2];
                float4 p1 = pp[c * 2 + 1], s1 = sp[c * 2 + 1];
                __half2 h0 = __floats2half2_rn(gelu_erf(p0.x + s0.x + d * sW0c[k0 + 0]),
                                               gelu_erf(p0.y + s0.y + d * sW0c[k0 + 1]));
                __half2 h1 = __floats2half2_rn(gelu_erf(p0.z + s0.z + d * sW0c[k0 + 2]),
                                               gelu_erf(p0.w + s0.w + d * sW0c[k0 + 3]));
                __half2 h2 = __floats2half2_rn(gelu_erf(p1.x + s1.x + d * sW0c[k0 + 4]),
                                               gelu_erf(p1.y + s1.y + d * sW0c[k0 + 5]));
                __half2 h3 = __floats2half2_rn(gelu_erf(p1.z + s1.z + d * sW0c[k0 + 6]),
                                               gelu_erf(p1.w + s1.w + d * sW0c[k0 + 7]));
                uint4 v = make_uint4(h2u(h0), h2u(h1), h2u(h2), h2u(h3));
                *(uint4*)(aBase + e * HROW + ((c ^ (e & 7)) << 4)) = v;
            }
        }
        __syncthreads();
        if (t < 4) {
            float c = 0.f;
#pragma unroll
            for (int kk = 0; kk < 32; kk++) c += sValid[t * 32 + kk];
            g_vcnt[tile * 4 + t] = c;
        }

        // ---- layer 2 GEMM (fp16)
        float acc[2][4][4];
#pragma unroll
        for (int i = 0; i < 2; i++)
#pragma unroll
            for (int j = 0; j < 4; j++)
#pragma unroll
                for (int q = 0; q < 4; q++) acc[i][j][q] = 0.f;
        warp_gemm_h32(sAaddr, sW1addr, acc, wm * 32, wn * 32, lane);
        __syncthreads();   // all h0 reads complete

        // ---- h1 = gelu(D + b1) back into A region (own 32-row band, own 32 cols)
#pragma unroll
        for (int i = 0; i < 2; i++)
#pragma unroll
            for (int j = 0; j < 4; j++) {
                int col = wn * 32 + j * 8 + 2 * tig;       // k index for next gemm
                int c = col >> 3, kb = (col & 7) * 2;
                int r0 = wm * 32 + i * 16 + gid;
                __half2 lo = __floats2half2_rn(gelu_erf(acc[i][j][0] + sB1[col]),
                                               gelu_erf(acc[i][j][1] + sB1[col + 1]));
                __half2 hi = __floats2half2_rn(gelu_erf(acc[i][j][2] + sB1[col]),
                                               gelu_erf(acc[i][j][3] + sB1[col + 1]));
                *(uint32_t*)(aBase + r0 * HROW + ((c ^ (r0 & 7)) << 4) + kb) = h2u(lo);
                int r1 = r0 + 8;
                *(uint32_t*)(aBase + r1 * HROW + ((c ^ (r1 & 7)) << 4) + kb) = h2u(hi);
            }
        __syncthreads();   // h1 visible

        // ---- layer 3 GEMM (fp16)
#pragma unroll
        for (int i = 0; i < 2; i++)
#pragma unroll
            for (int j = 0; j < 4; j++)
#pragma unroll
                for (int q = 0; q < 4; q++) acc[i][j][q] = 0.f;
        warp_gemm_h32(sAaddr, sW2addr, acc, wm * 32, wn * 32, lane);

        // ---- epilogue: gelu + valid mask + sum over the 32 edges of node wm
        int gout = tile * 4 + wm;
#pragma unroll
        for (int j = 0; j < 4; j++) {
            int col = wn * 32 + j * 8 + 2 * tig;
            float be = sB2[col], bo = sB2[col + 1];
            float se = 0.f, so = 0.f;
#pragma unroll
            for (int i = 0; i < 2; i++) {
                int r0 = wm * 32 + i * 16 + gid;
                float v0 = sValid[r0], v1 = sValid[r0 + 8];
                se += gelu_erf(acc[i][j][0] + be) * v0 + gelu_erf(acc[i][j][2] + be) * v1;
                so += gelu_erf(acc[i][j][1] + bo) * v0 + gelu_erf(acc[i][j][3] + bo) * v1;
            }
            se += __shfl_xor_sync(0xffffffffu, se, 16);
            so += __shfl_xor_sync(0xffffffffu, so, 16);
            se += __shfl_xor_sync(0xffffffffu, se, 8);
            so += __shfl_xor_sync(0xffffffffu, so, 8);
            se += __shfl_xor_sync(0xffffffffu, se, 4);
            so += __shfl_xor_sync(0xffffffffu, so, 4);
            if (gid == 0) *(float2*)(g_msum + (size_t)gout * H_ + col) = make_float2(se, so);
        }
        __syncthreads();   // protect sA/sValid before next tile
    }
}

// ------------------------------------------------- norm stage 1: upd + partial stats
__global__ void __launch_bounds__(256)
norm1_kernel(const float* __restrict__ atom, const float* __restrict__ mask) {
    int b = blockIdx.x >> 8, chunk = blockIdx.x & 255;
    int t = threadIdx.x, h = t & 127, half = t >> 7;
    int n0 = chunk * 16;

    float s = 0.f, s2 = 0.f;
    for (int n = n0 + half; n < n0 + 16; n += 2) {
        int g = b * N_ + n;
        float m = mask[g];
        float vc = fmaxf(g_vcnt[g], 1.0f);
        float u = (atom[(size_t)g * H_ + h] + g_msum[(size_t)g * H_ + h] / vc) * m;
        g_upd[(size_t)g * H_ + h] = u;
        s += u; s2 += u * u;
    }
    __shared__ float sS[256], sS2[256], sC[16];
    sS[t] = s; sS2[t] = s2;
    if (t < 16) sC[t] = mask[b * N_ + n0 + t];
    __syncthreads();
    if (t < 128) {
        g_ps [(b * NCH + chunk) * H_ + t] = sS[t] + sS[t + 128];
        g_ps2[(b * NCH + chunk) * H_ + t] = sS2[t] + sS2[t + 128];
    }
    if (t == 0) {
        float c = 0.f;
#pragma unroll
        for (int i = 0; i < 16; i++) c += sC[i];
        g_pc[b * NCH + chunk] = c;
    }
}

// ------------------------------------------------- norm stage 2: finalize stats
__global__ void __launch_bounds__(128)
norm_mid_kernel() {
    int b = blockIdx.x, h = threadIdx.x;
    float S = 0.f, S2 = 0.f;
#pragma unroll 8
    for (int c = 0; c < NCH; c++) {
        S  += g_ps [(b * NCH + c) * H_ + h];
        S2 += g_ps2[(b * NCH + c) * H_ + h];
    }
    __shared__ float sCnt;
    if (h < 32) {
        float cc = 0.f;
#pragma unroll
        for (int c = h; c < NCH; c += 32) cc += g_pc[b * NCH + c];
#pragma unroll
        for (int off = 16; off > 0; off >>= 1) cc += __shfl_xor_sync(0xffffffffu, cc, off);
        if (h == 0) sCnt = cc;
    }
    __syncthreads();
    float C = sCnt;
    if (C == 0.f) C = 1.f;
    float mean = S / C;
    float var  = (S2 - 2.f * mean * S + (float)N_ * mean * mean) / C;
    g_mean[b * H_ + h] = mean;
    g_rstd[b * H_ + h] = rsqrtf(var + 1e-5f);
}

// ------------------------------------------------- norm stage 3: normalize
__global__ void __launch_bounds__(256)
norm2_kernel(const float* __restrict__ mask, const float* __restrict__ scale,
             const float* __restrict__ shift, float* __restrict__ out) {
    int b = blockIdx.x >> 8, chunk = blockIdx.x & 255;
    int t = threadIdx.x, h = t & 127, half = t >> 7;
    float mean = g_mean[b * H_ + h], rstd = g_rstd[b * H_ + h];
    float sc = __ldg(scale + h), sh = __ldg(shift + h);
    int n0 = chunk * 16;
    for (int n = n0 + half; n < n0 + 16; n += 2) {
        int g = b * N_ + n;
        float m = mask[g];
        float u = g_upd[(size_t)g * H_ + h];
        out[(size_t)g * H_ + h] = ((u - mean) * rstd * sc + sh) * m;
    }
}

// ------------------------------------------------- tuple tail copies
__global__ void tail_a_kernel(const float* __restrict__ mask, const float* __restrict__ dist,
                              float* __restrict__ out, int out_size) {
    int i = blockIdx.x * blockDim.x + threadIdx.x;
    const int off0 = NODES * H_;
    if (i < NODES) {
        int o = off0 + i;
        if (o < out_size) out[o] = mask[i];
    } else if (i < NODES + EDGES) {
        int o = off0 + i;
        if (o < out_size) out[o] = dist[i - NODES];
    }
}
__global__ void tail_b_kernel(const int* __restrict__ eidx, float* __restrict__ out,
                              int out_size) {
    int i = blockIdx.x * blockDim.x + threadIdx.x;
    const int off0 = NODES * H_ + NODES + EDGES;
    if (i < EDGES) {
        int o = off0 + i;
        if (o < out_size) out[o] = (float)eidx[i];
    }
}

// ------------------------------------------------- launch
extern "C" void kernel_launch(void* const* d_in, const int* in_sizes, int n_in,
                              void* d_out, int out_size) {
    const float* atom  = (const float*)d_in[0];
    const float* mask  = (const float*)d_in[1];
    const float* dist  = (const float*)d_in[2];
    const int*   eidx  = (const int*)d_in[3];
    const float* W0    = (const float*)d_in[4];
    const float* b0    = (const float*)d_in[5];
    const float* W1    = (const float*)d_in[6];
    const float* b1    = (const float*)d_in[7];
    const float* W2    = (const float*)d_in[8];
    const float* b2    = (const float*)d_in[9];
    const float* scale = (const float*)d_in[10];
    const float* shift = (const float*)d_in[11];
    float* out = (float*)d_out;

    cudaFuncSetAttribute(proj_kernel, cudaFuncAttributeMaxDynamicSharedMemorySize, PROJ_SMEM);
    cudaFuncSetAttribute(edge_kernel, cudaFuncAttributeMaxDynamicSharedMemorySize, EDGE_SMEM);

    // launch order chosen so edge_kernel is the 4th launch (ncu -s 5 window)
    tail_a_kernel<<<(NODES + EDGES + 255) / 256, 256>>>(mask, dist, out, out_size);
    tail_b_kernel<<<(EDGES + 255) / 256, 256>>>(eidx, out, out_size);
    proj_kernel<<<NODES / 128, 256, PROJ_SMEM>>>(atom, mask, W0, b0);
    edge_kernel<<<296, 512, EDGE_SMEM>>>(dist, eidx, W0, W1, b1, W2, b2);
    norm1_kernel<<<B_ * NCH, 256>>>(atom, mask);
    norm_mid_kernel<<<B_, 128>>>();
    norm2_kernel<<<B_ * NCH, 256>>>(mask, scale, shift, out);
}

// round 7
// speedup vs baseline: 1.2086x; 1.2086x over previous
#include <cuda_runtime.h>
#include <cuda_fp16.h>
#include <cstdint>

// Problem constants
#define B_      4
#define N_      4096
#define K_      32
#define H_      128
#define NODES   (B_ * N_)        // 16384
#define EDGES   (NODES * K_)     // 524288
#define NTILES  (NODES / 4)      // 4096 tiles of 128 edges (4 nodes)
#define NCH     256              // chunks per batch for norm (16 nodes each)
#define LDS2    144              // proj kernel smem row stride (floats)

// edge kernel: 3 half-precision regions [128 rows x 256B], XOR-swizzled
#define HROW    256              // bytes per row (128 halfs)
#define HREG    (128 * HROW)     // 32768 B
static const int EDGE_SMEM = 3 * HREG + 1024;
static const int PROJ_SMEM = 3 * 128 * LDS2 * 4;

// Scratch (no cudaMalloc allowed)
__device__ float g_P[NODES * H_];     // enc @ W0[:H]; reused as g_upd after edge kernel
__device__ float g_S[NODES * H_];     // enc @ W0[H:2H] + b0
__device__ float g_msum[NODES * H_];
__device__ float g_vcnt[NODES];
__device__ float g_ps [B_ * NCH * H_];
__device__ float g_ps2[B_ * NCH * H_];
__device__ float g_pc [B_ * NCH];
__device__ float g_mean[B_ * H_];
__device__ float g_rstd[B_ * H_];
#define g_upd g_P

// ---------------------------------------------------------------- helpers
__device__ __forceinline__ float to_tf32(float x) {
    uint32_t u;
    asm("cvt.rna.tf32.f32 %0, %1;" : "=r"(u) : "f"(x));
    return __uint_as_float(u);
}
// Branch-free erf-GELU: Abramowitz-Stegun 7.1.26 (|eps| <= 1.5e-7 on erf).
// gelu(x) = 0.5*x*(1 + erf(x/sqrt(2)))
__device__ __forceinline__ float gelu_fast(float x) {
    float az = fabsf(x) * 0.70710678118654752f;
    float s  = az * az;
    float e  = __expf(-s);                               // MUFU.EX2 path
    float t  = __fdividef(1.0f, fmaf(0.3275911f, az, 1.0f));  // MUFU.RCP path
    float p  = fmaf(1.061405429f, t, -1.453152027f);
    p = fmaf(p, t, 1.421413741f);
    p = fmaf(p, t, -0.284496736f);
    p = fmaf(p, t, 0.254829592f);
    p = p * t;
    float erfv = copysignf(fmaf(-p, e, 1.0f), x);        // sign(x)*(1 - p*e)
    float hx = 0.5f * x;
    return fmaf(hx, erfv, hx);
}
__device__ __forceinline__ int pidx(int k) {   // proj kernel permuted-k layout
    return ((k >> 4) << 4) + ((k & 3) << 2) + ((k >> 2) & 3);
}
__device__ __forceinline__ uint32_t smem_u32(const void* p) {
    uint32_t r;
    asm("{ .reg .u64 t; cvta.to.shared.u64 t, %1; cvt.u32.u64 %0, t; }" : "=r"(r) : "l"(p));
    return r;
}
__device__ __forceinline__ uint32_t h2u(__half2 h) { return *(uint32_t*)&h; }

#define LDSM_X4(r0, r1, r2, r3, addr) \
    asm volatile("ldmatrix.sync.aligned.m8n8.x4.shared.b16 {%0,%1,%2,%3}, [%4];" \
                 : "=r"(r0), "=r"(r1), "=r"(r2), "=r"(r3) : "r"(addr))

__device__ __forceinline__ void mma16(float* c, const uint32_t* a, const uint32_t* b) {
    asm volatile(
        "mma.sync.aligned.m16n8k16.row.col.f32.f16.f16.f32 "
        "{%0,%1,%2,%3},{%4,%5,%6,%7},{%8,%9},{%0,%1,%2,%3};\n"
        : "+f"(c[0]), "+f"(c[1]), "+f"(c[2]), "+f"(c[3])
        : "r"(a[0]), "r"(a[1]), "r"(a[2]), "r"(a[3]), "r"(b[0]), "r"(b[1]));
}

// fp16 warp GEMM: warp tile 32 rows x 64 cols, K=128, via ldmatrix.x4.
// A region rows = edges, W region rows = output cols; both [row][k] halfs,
// 16B chunk swizzle: chunk' = chunk ^ (row & 7).
__device__ __forceinline__ void warp_gemm_h(uint32_t sA, uint32_t sW,
                                            float (&acc)[2][8][4],
                                            int rowA0, int colB0, int lane) {
    int q = lane & 7, mat = lane >> 3;
    int kaddA = mat >> 1;          // A: mats 0,1 -> kchunk+0 ; 2,3 -> +1
    int kaddB = mat & 1;           // B: mats 0,2 -> kchunk+0 ; 1,3 -> +1
    uint32_t aBase[2]; int aR7[2];
#pragma unroll
    for (int i = 0; i < 2; i++) {
        int row = rowA0 + i * 16 + q + (mat & 1) * 8;
        aBase[i] = sA + row * HROW;
        aR7[i] = (row & 7) << 4;
    }
    uint32_t bBase[4]; int bR7[4];
#pragma unroll
    for (int p = 0; p < 4; p++) {
        int n = colB0 + p * 16 + q + (mat >> 1) * 8;
        bBase[p] = sW + n * HROW;
        bR7[p] = (n & 7) << 4;
    }
#pragma unroll
    for (int s = 0; s < 8; s++) {
        uint32_t a[2][4];
#pragma unroll
        for (int i = 0; i < 2; i++)
            LDSM_X4(a[i][0], a[i][1], a[i][2], a[i][3],
                    aBase[i] + ((((2 * s + kaddA) << 4)) ^ aR7[i]));
#pragma unroll
        for (int p = 0; p < 4; p++) {
            uint32_t b[4];
            LDSM_X4(b[0], b[1], b[2], b[3],
                    bBase[p] + ((((2 * s + kaddB) << 4)) ^ bR7[p]));
#pragma unroll
            for (int i = 0; i < 2; i++) {
                mma16(acc[i][2 * p],     a[i], &b[0]);
                mma16(acc[i][2 * p + 1], a[i], &b[2]);
            }
        }
    }
}

// ---------------------------------------------------------------- proj (tf32 mma.sync)
__device__ __forceinline__ void mma8(float* c, const uint32_t* a, const uint32_t* b) {
    asm volatile(
        "mma.sync.aligned.m16n8k8.row.col.f32.tf32.tf32.f32 "
        "{%0,%1,%2,%3},{%4,%5,%6,%7},{%8,%9},{%0,%1,%2,%3};\n"
        : "+f"(c[0]), "+f"(c[1]), "+f"(c[2]), "+f"(c[3])
        : "r"(a[0]), "r"(a[1]), "r"(a[2]), "r"(a[3]), "r"(b[0]), "r"(b[1]));
}
template <int NJ>
__device__ __forceinline__ void warp_gemm_p(const float* __restrict__ sAv,
                                            const float* __restrict__ sWv,
                                            float (&acc)[2][NJ][4],
                                            int rowA0, int colB0, int gid, int tig) {
#pragma unroll
    for (int j = 0; j < 8; j++) {
        int fo = (j * 4 + tig) * 4;
        float4 a4[2][2];
#pragma unroll
        for (int i = 0; i < 2; i++) {
            const float* ap = sAv + (rowA0 + i * 16 + gid) * LDS2 + fo;
            a4[i][0] = *(const float4*)ap;
            a4[i][1] = *(const float4*)(ap + 8 * LDS2);
        }
#pragma unroll
        for (int jj = 0; jj < NJ; jj++) {
            float4 b4 = *(const float4*)(sWv + (colB0 + jj * 8 + gid) * LDS2 + fo);
            uint32_t b0[2] = {__float_as_uint(b4.x), __float_as_uint(b4.y)};
            uint32_t b1[2] = {__float_as_uint(b4.z), __float_as_uint(b4.w)};
#pragma unroll
            for (int i = 0; i < 2; i++) {
                uint32_t a0[4] = {__float_as_uint(a4[i][0].x), __float_as_uint(a4[i][1].x),
                                  __float_as_uint(a4[i][0].y), __float_as_uint(a4[i][1].y)};
                uint32_t a1[4] = {__float_as_uint(a4[i][0].z), __float_as_uint(a4[i][1].z),
                                  __float_as_uint(a4[i][0].w), __float_as_uint(a4[i][1].w)};
                mma8(acc[i][jj], a0, b0);
                mma8(acc[i][jj], a1, b1);
            }
        }
    }
}

__global__ void __launch_bounds__(256, 1)
proj_kernel(const float* __restrict__ atom, const float* __restrict__ mask,
            const float* __restrict__ W0, const float* __restrict__ b0) {
    extern __shared__ float smem[];
    float* sA  = smem;
    float* sWa = smem + 128 * LDS2;
    float* sWb = smem + 2 * 128 * LDS2;
    __shared__ float sB0[128];

    int t = threadIdx.x, lane = t & 31, w = t >> 5;
    int wm = w >> 1, wn = w & 1, gid = lane >> 2, tig = lane & 3;

    if (t < 128) sB0[t] = b0[t];
    for (int i = t; i < 128 * 128; i += 256) {
        int k = i >> 7, n = i & 127;
        int p = n * LDS2 + pidx(k);
        sWa[p] = to_tf32(W0[i]);
        sWb[p] = to_tf32(W0[128 * 128 + i]);
    }
    {
        int r = t >> 1;
        int grow = blockIdx.x * 128 + r;
        float m = mask[grow];
        int c0 = (t & 1) * 64;
        const float4* src = (const float4*)(atom + (size_t)grow * H_);
#pragma unroll 4
        for (int c = c0; c < c0 + 64; c += 4) {
            float4 a = src[c >> 2];
            int base = r * LDS2 + ((c >> 4) << 4) + ((c >> 2) & 3);
            sA[base + 0]  = to_tf32(a.x * m);
            sA[base + 4]  = to_tf32(a.y * m);
            sA[base + 8]  = to_tf32(a.z * m);
            sA[base + 12] = to_tf32(a.w * m);
        }
    }
    __syncthreads();

    float acc[2][8][4];
#pragma unroll
    for (int i = 0; i < 2; i++)
#pragma unroll
        for (int j = 0; j < 8; j++)
#pragma unroll
            for (int q = 0; q < 4; q++) acc[i][j][q] = 0.f;
    warp_gemm_p<8>(sA, sWa, acc, wm * 32, wn * 64, gid, tig);
#pragma unroll
    for (int i = 0; i < 2; i++)
#pragma unroll
        for (int j = 0; j < 8; j++) {
            int col = wn * 64 + j * 8 + 2 * tig;
            int r = blockIdx.x * 128 + wm * 32 + i * 16 + gid;
            *(float2*)(g_P + (size_t)r * H_ + col)       = make_float2(acc[i][j][0], acc[i][j][1]);
            *(float2*)(g_P + (size_t)(r + 8) * H_ + col) = make_float2(acc[i][j][2], acc[i][j][3]);
        }
#pragma unroll
    for (int i = 0; i < 2; i++)
#pragma unroll
        for (int j = 0; j < 8; j++)
#pragma unroll
            for (int q = 0; q < 4; q++) acc[i][j][q] = 0.f;
    warp_gemm_p<8>(sA, sWb, acc, wm * 32, wn * 64, gid, tig);
#pragma unroll
    for (int i = 0; i < 2; i++)
#pragma unroll
        for (int j = 0; j < 8; j++) {
            int col = wn * 64 + j * 8 + 2 * tig;
            int r = blockIdx.x * 128 + wm * 32 + i * 16 + gid;
            float be = sB0[col], bo = sB0[col + 1];
            *(float2*)(g_S + (size_t)r * H_ + col)       = make_float2(acc[i][j][0] + be, acc[i][j][1] + bo);
            *(float2*)(g_S + (size_t)(r + 8) * H_ + col) = make_float2(acc[i][j][2] + be, acc[i][j][3] + bo);
        }
}

// ------------------------------------------------- persistent fused edge MLP (fp16 + ldmatrix)
// 256 threads = 8 warps (4 row-bands x 2 col-halves), 2 CTAs per SM.  (R5 tiling.)
__global__ void __launch_bounds__(256, 2)
edge_kernel(const float* __restrict__ dist, const int* __restrict__ eidx,
            const float* __restrict__ W0, const float* __restrict__ W1,
            const float* __restrict__ b1, const float* __restrict__ W2,
            const float* __restrict__ b2) {
    extern __shared__ char dsm[];
    __shared__ float sValid[128], sW0c[128], sB1[128], sB2[128];

    uint32_t dynBase = smem_u32(dsm);
    uint32_t pad = (1024u - (dynBase & 1023u)) & 1023u;
    uint32_t sAaddr  = dynBase + pad;
    uint32_t sW1addr = sAaddr + HREG;
    uint32_t sW2addr = sAaddr + 2 * HREG;
    char* aBase  = dsm + pad;
    char* w1Base = aBase + HREG;
    char* w2Base = aBase + 2 * HREG;

    int t = threadIdx.x, lane = t & 31, w = t >> 5;
    int wm = w >> 1, wn = w & 1, gid = lane >> 2, tig = lane & 3;

    if (t < 128) {
        sW0c[t] = W0[256 * 128 + t];
        sB1[t]  = b1[t];
        sB2[t]  = b2[t];
    }
    // one-time weight staging: region row n holds W[.][n] over k, swizzled halfs
    for (int i = t; i < 128 * 128; i += 256) {
        int k = i >> 7, n = i & 127;
        uint32_t off = (uint32_t)(n * HROW + ((((k >> 3) ^ (n & 7)) << 4)) + (k & 7) * 2);
        *(__half*)(w1Base + off) = __float2half_rn(W1[i]);
        *(__half*)(w2Base + off) = __float2half_rn(W2[i]);
    }
    __syncthreads();

    for (int tile = blockIdx.x; tile < NTILES; tile += gridDim.x) {
        // ---- phase A: gather + layer-1 epilogue -> h0 halfs into A region
        {
            int e = t >> 1;
            int gnode = tile * 4 + (e >> 5);
            int eid = gnode * K_ + (e & 31);
            int idx = __ldg(eidx + eid);
            float valid = (idx >= 0) ? 1.0f : 0.0f;
            int src = (gnode & ~(N_ - 1)) + (idx >= 0 ? idx : 0);
            float d = __ldg(dist + eid);
            if ((t & 1) == 0) sValid[e] = valid;
            const float4* pp = (const float4*)(g_P + (size_t)src * H_);
            const float4* sp = (const float4*)(g_S + (size_t)gnode * H_);
            int cbase = (t & 1) * 8;
#pragma unroll
            for (int i = 0; i < 8; i++) {
                int c = cbase + i;
                int k0 = c * 8;
                float4 p0 = pp[c * 2],     s0 = sp[c * 2];
                float4 p1 = pp[c * 2 + 1], s1 = sp[c * 2 + 1];
                __half2 h0 = __floats2half2_rn(gelu_fast(p0.x + s0.x + d * sW0c[k0 + 0]),
                                               gelu_fast(p0.y + s0.y + d * sW0c[k0 + 1]));
                __half2 h1 = __floats2half2_rn(gelu_fast(p0.z + s0.z + d * sW0c[k0 + 2]),
                                               gelu_fast(p0.w + s0.w + d * sW0c[k0 + 3]));
                __half2 h2 = __floats2half2_rn(gelu_fast(p1.x + s1.x + d * sW0c[k0 + 4]),
                                               gelu_fast(p1.y + s1.y + d * sW0c[k0 + 5]));
                __half2 h3 = __floats2half2_rn(gelu_fast(p1.z + s1.z + d * sW0c[k0 + 6]),
                                               gelu_fast(p1.w + s1.w + d * sW0c[k0 + 7]));
                uint4 v = make_uint4(h2u(h0), h2u(h1), h2u(h2), h2u(h3));
                *(uint4*)(aBase + e * HROW + ((c ^ (e & 7)) << 4)) = v;
            }
        }
        __syncthreads();
        if (t < 4) {
            float c = 0.f;
#pragma unroll
            for (int kk = 0; kk < 32; kk++) c += sValid[t * 32 + kk];
            g_vcnt[tile * 4 + t] = c;
        }

        // ---- layer 2 GEMM (fp16)
        float acc[2][8][4];
#pragma unroll
        for (int i = 0; i < 2; i++)
#pragma unroll
            for (int j = 0; j < 8; j++)
#pragma unroll
                for (int q = 0; q < 4; q++) acc[i][j][q] = 0.f;
        warp_gemm_h(sAaddr, sW1addr, acc, wm * 32, wn * 64, lane);
        __syncthreads();   // all h0 reads complete

        // ---- h1 = gelu(D + b1) back into A region (own 32-row band, own 64 cols)
#pragma unroll
        for (int i = 0; i < 2; i++)
#pragma unroll
            for (int j = 0; j < 8; j++) {
                int col = wn * 64 + j * 8 + 2 * tig;       // k index for next gemm
                int c = col >> 3, kb = (col & 7) * 2;
                int r0 = wm * 32 + i * 16 + gid;
                __half2 lo = __floats2half2_rn(gelu_fast(acc[i][j][0] + sB1[col]),
                                               gelu_fast(acc[i][j][1] + sB1[col + 1]));
                __half2 hi = __floats2half2_rn(gelu_fast(acc[i][j][2] + sB1[col]),
                                               gelu_fast(acc[i][j][3] + sB1[col + 1]));
                *(uint32_t*)(aBase + r0 * HROW + ((c ^ (r0 & 7)) << 4) + kb) = h2u(lo);
                int r1 = r0 + 8;
                *(uint32_t*)(aBase + r1 * HROW + ((c ^ (r1 & 7)) << 4) + kb) = h2u(hi);
            }
        __syncthreads();   // h1 visible

        // ---- layer 3 GEMM (fp16)
#pragma unroll
        for (int i = 0; i < 2; i++)
#pragma unroll
            for (int j = 0; j < 8; j++)
#pragma unroll
                for (int q = 0; q < 4; q++) acc[i][j][q] = 0.f;
        warp_gemm_h(sAaddr, sW2addr, acc, wm * 32, wn * 64, lane);

        // ---- epilogue: gelu + valid mask + sum over the 32 edges of node wm
        int gout = tile * 4 + wm;
#pragma unroll
        for (int j = 0; j < 8; j++) {
            int col = wn * 64 + j * 8 + 2 * tig;
            float be = sB2[col], bo = sB2[col + 1];
            float se = 0.f, so = 0.f;
#pragma unroll
            for (int i = 0; i < 2; i++) {
                int r0 = wm * 32 + i * 16 + gid;
                float v0 = sValid[r0], v1 = sValid[r0 + 8];
                se += gelu_fast(acc[i][j][0] + be) * v0 + gelu_fast(acc[i][j][2] + be) * v1;
                so += gelu_fast(acc[i][j][1] + bo) * v0 + gelu_fast(acc[i][j][3] + bo) * v1;
            }
            se += __shfl_xor_sync(0xffffffffu, se, 16);
            so += __shfl_xor_sync(0xffffffffu, so, 16);
            se += __shfl_xor_sync(0xffffffffu, se, 8);
            so += __shfl_xor_sync(0xffffffffu, so, 8);
            se += __shfl_xor_sync(0xffffffffu, se, 4);
            so += __shfl_xor_sync(0xffffffffu, so, 4);
            if (gid == 0) *(float2*)(g_msum + (size_t)gout * H_ + col) = make_float2(se, so);
        }
        __syncthreads();   // protect sA/sValid before next tile
    }
}

// ------------------------------------------------- norm stage 1: upd + partial stats
__global__ void __launch_bounds__(256)
norm1_kernel(const float* __restrict__ atom, const float* __restrict__ mask) {
    int b = blockIdx.x >> 8, chunk = blockIdx.x & 255;
    int t = threadIdx.x, h = t & 127, half = t >> 7;
    int n0 = chunk * 16;

    float s = 0.f, s2 = 0.f;
    for (int n = n0 + half; n < n0 + 16; n += 2) {
        int g = b * N_ + n;
        float m = mask[g];
        float vc = fmaxf(g_vcnt[g], 1.0f);
        float u = (atom[(size_t)g * H_ + h] + g_msum[(size_t)g * H_ + h] / vc) * m;
        g_upd[(size_t)g * H_ + h] = u;
        s += u; s2 += u * u;
    }
    __shared__ float sS[256], sS2[256], sC[16];
    sS[t] = s; sS2[t] = s2;
    if (t < 16) sC[t] = mask[b * N_ + n0 + t];
    __syncthreads();
    if (t < 128) {
        g_ps [(b * NCH + chunk) * H_ + t] = sS[t] + sS[t + 128];
        g_ps2[(b * NCH + chunk) * H_ + t] = sS2[t] + sS2[t + 128];
    }
    if (t == 0) {
        float c = 0.f;
#pragma unroll
        for (int i = 0; i < 16; i++) c += sC[i];
        g_pc[b * NCH + chunk] = c;
    }
}

// ------------------------------------------------- norm stage 2: finalize stats
__global__ void __launch_bounds__(128)
norm_mid_kernel() {
    int b = blockIdx.x, h = threadIdx.x;
    float S = 0.f, S2 = 0.f;
#pragma unroll 8
    for (int c = 0; c < NCH; c++) {
        S  += g_ps [(b * NCH + c) * H_ + h];
        S2 += g_ps2[(b * NCH + c) * H_ + h];
    }
    __shared__ float sCnt;
    if (h < 32) {
        float cc = 0.f;
#pragma unroll
        for (int c = h; c < NCH; c += 32) cc += g_pc[b * NCH + c];
#pragma unroll
        for (int off = 16; off > 0; off >>= 1) cc += __shfl_xor_sync(0xffffffffu, cc, off);
        if (h == 0) sCnt = cc;
    }
    __syncthreads();
    float C = sCnt;
    if (C == 0.f) C = 1.f;
    float mean = S / C;
    float var  = (S2 - 2.f * mean * S + (float)N_ * mean * mean) / C;
    g_mean[b * H_ + h] = mean;
    g_rstd[b * H_ + h] = rsqrtf(var + 1e-5f);
}

// ------------------------------------------------- norm stage 3: normalize
__global__ void __launch_bounds__(256)
norm2_kernel(const float* __restrict__ mask, const float* __restrict__ scale,
             const float* __restrict__ shift, float* __restrict__ out) {
    int b = blockIdx.x >> 8, chunk = blockIdx.x & 255;
    int t = threadIdx.x, h = t & 127, half = t >> 7;
    float mean = g_mean[b * H_ + h], rstd = g_rstd[b * H_ + h];
    float sc = __ldg(scale + h), sh = __ldg(shift + h);
    int n0 = chunk * 16;
    for (int n = n0 + half; n < n0 + 16; n += 2) {
        int g = b * N_ + n;
        float m = mask[g];
        float u = g_upd[(size_t)g * H_ + h];
        out[(size_t)g * H_ + h] = ((u - mean) * rstd * sc + sh) * m;
    }
}

// ------------------------------------------------- tuple tail copies
__global__ void tail_a_kernel(const float* __restrict__ mask, const float* __restrict__ dist,
                              float* __restrict__ out, int out_size) {
    int i = blockIdx.x * blockDim.x + threadIdx.x;
    const int off0 = NODES * H_;
    if (i < NODES) {
        int o = off0 + i;
        if (o < out_size) out[o] = mask[i];
    } else if (i < NODES + EDGES) {
        int o = off0 + i;
        if (o < out_size) out[o] = dist[i - NODES];
    }
}
__global__ void tail_b_kernel(const int* __restrict__ eidx, float* __restrict__ out,
                              int out_size) {
    int i = blockIdx.x * blockDim.x + threadIdx.x;
    const int off0 = NODES * H_ + NODES + EDGES;
    if (i < EDGES) {
        int o = off0 + i;
        if (o < out_size) out[o] = (float)eidx[i];
    }
}

// ------------------------------------------------- launch
extern "C" void kernel_launch(void* const* d_in, const int* in_sizes, int n_in,
                              void* d_out, int out_size) {
    const float* atom  = (const float*)d_in[0];
    const float* mask  = (const float*)d_in[1];
    const float* dist  = (const float*)d_in[2];
    const int*   eidx  = (const int*)d_in[3];
    const float* W0    = (const float*)d_in[4];
    const float* b0    = (const float*)d_in[5];
    const float* W1    = (const float*)d_in[6];
    const float* b1    = (const float*)d_in[7];
    const float* W2    = (const float*)d_in[8];
    const float* b2    = (const float*)d_in[9];
    const float* scale = (const float*)d_in[10];
    const float* shift = (const float*)d_in[11];
    float* out = (float*)d_out;

    cudaFuncSetAttribute(proj_kernel, cudaFuncAttributeMaxDynamicSharedMemorySize, PROJ_SMEM);
    cudaFuncSetAttribute(edge_kernel, cudaFuncAttributeMaxDynamicSharedMemorySize, EDGE_SMEM);

    // launch order chosen so edge_kernel is the 4th launch (ncu -s 5 window)
    tail_a_kernel<<<(NODES + EDGES + 255) / 256, 256>>>(mask, dist, out, out_size);
    tail_b_kernel<<<(EDGES + 255) / 256, 256>>>(eidx, out, out_size);
    proj_kernel<<<NODES / 128, 256, PROJ_SMEM>>>(atom, mask, W0, b0);
    edge_kernel<<<296, 256, EDGE_SMEM>>>(dist, eidx, W0, W1, b1, W2, b2);
    norm1_kernel<<<B_ * NCH, 256>>>(atom, mask);
    norm_mid_kernel<<<B_, 128>>>();
    norm2_kernel<<<B_ * NCH, 256>>>(mask, scale, shift, out);
}